// round 1
// baseline (speedup 1.0000x reference)
#include <cuda_runtime.h>
#include <cuda_bf16.h>
#include <math_constants.h>

// Problem constants (fixed by the dataset)
#define N_NODES 50000
#define N_EDGES 1600000
#define D 128

// ---------------- scratch (device globals; no allocation allowed) ----------
__device__ float g_z[N_NODES * D];      // per-layer linear output
__device__ float g_h[N_NODES * D];      // per-layer aggregated output (ping)
__device__ float g_asrc[N_NODES];
__device__ float g_adst[N_NODES];
__device__ int   g_deg[N_NODES];
__device__ int   g_cur[N_NODES];
__device__ int   g_off[N_NODES + 1];
__device__ int   g_csr_src[N_EDGES];    // src node id, grouped by dst

// ---------------- CSR build ------------------------------------------------
__global__ void zero_kernel(int* a, int* b, int n) {
    int i = blockIdx.x * blockDim.x + threadIdx.x;
    if (i < n) { a[i] = 0; b[i] = 0; }
}

__global__ void hist_kernel(const int* __restrict__ dst, int* __restrict__ deg, int E) {
    int i = blockIdx.x * blockDim.x + threadIdx.x;
    if (i < E) atomicAdd(&deg[dst[i]], 1);
}

// single-block exclusive scan, 1024 threads, 4 elems/thread per chunk
__global__ void scan_kernel(const int* __restrict__ deg, int* __restrict__ off, int n) {
    __shared__ int warp_sums[32];
    __shared__ int s_carry;
    int tid = threadIdx.x, lane = tid & 31, wid = tid >> 5;
    if (tid == 0) s_carry = 0;
    __syncthreads();
    const int CH = 4096;
    for (int base = 0; base < n; base += CH) {
        int i0 = base + tid * 4;
        int v[4];
#pragma unroll
        for (int u = 0; u < 4; u++) v[u] = (i0 + u < n) ? deg[i0 + u] : 0;
        int sum = v[0] + v[1] + v[2] + v[3];
        // inclusive warp scan of per-thread sums
        int x = sum;
#pragma unroll
        for (int o = 1; o < 32; o <<= 1) {
            int y = __shfl_up_sync(0xffffffffu, x, o);
            if (lane >= o) x += y;
        }
        if (lane == 31) warp_sums[wid] = x;
        __syncthreads();
        if (wid == 0) {
            int w = warp_sums[lane];
#pragma unroll
            for (int o = 1; o < 32; o <<= 1) {
                int y = __shfl_up_sync(0xffffffffu, w, o);
                if (lane >= o) w += y;
            }
            warp_sums[lane] = w;
        }
        __syncthreads();
        int excl = x - sum + (wid ? warp_sums[wid - 1] : 0) + s_carry;
        int run = excl;
#pragma unroll
        for (int u = 0; u < 4; u++) {
            if (i0 + u < n) off[i0 + u] = run;
            run += v[u];
        }
        __syncthreads();
        if (tid == 0) s_carry += warp_sums[31];
        __syncthreads();
    }
    if (threadIdx.x == 0) off[n] = s_carry;
}

__global__ void scatter_kernel(const int* __restrict__ src, const int* __restrict__ dst,
                               const int* __restrict__ off, int* __restrict__ cur,
                               int* __restrict__ csr_src, int E) {
    int i = blockIdx.x * blockDim.x + threadIdx.x;
    if (i >= E) return;
    int d = dst[i];
    int p = off[d] + atomicAdd(&cur[d], 1);
    csr_src[p] = src[i];
}

// ---------------- GEMM: Z = act(X) @ W^T + b  (X:[n,128], W:[128,128]) ------
// BM=BN=128, BK=32, 256 threads, 8x8 micro-tile. Tiles stored transposed
// (k-major) so compute-phase LDS are aligned float4, conflict-free.
template <bool RELU>
__global__ __launch_bounds__(256) void gemm_kernel(
    const float* __restrict__ X, const float* __restrict__ W,
    const float* __restrict__ bias, float* __restrict__ Z, int n)
{
    __shared__ float xs[32][128];
    __shared__ float ws[32][128];
    int tid = threadIdx.x;
    int tx = tid & 15, ty = tid >> 4;
    int row0 = blockIdx.x * 128;
    int r  = tid & 127;          // row (X) / out (W) index inside tile
    int kb = (tid >> 7) * 16;    // 16-wide k slab

    float acc[8][8];
#pragma unroll
    for (int i = 0; i < 8; i++)
#pragma unroll
        for (int j = 0; j < 8; j++) acc[i][j] = 0.f;

    for (int k0 = 0; k0 < 128; k0 += 32) {
        float4 vx[4], vw[4];
        int grow = row0 + r;
        bool xok = grow < n;
#pragma unroll
        for (int u4 = 0; u4 < 4; u4++) {
            vx[u4] = xok ? *(const float4*)(X + (size_t)grow * D + k0 + kb + u4 * 4)
                         : make_float4(0.f, 0.f, 0.f, 0.f);
            vw[u4] = *(const float4*)(W + (size_t)r * D + k0 + kb + u4 * 4);
            if (RELU) {
                vx[u4].x = fmaxf(vx[u4].x, 0.f);
                vx[u4].y = fmaxf(vx[u4].y, 0.f);
                vx[u4].z = fmaxf(vx[u4].z, 0.f);
                vx[u4].w = fmaxf(vx[u4].w, 0.f);
            }
        }
        __syncthreads();  // protect previous compute before overwrite
#pragma unroll
        for (int u4 = 0; u4 < 4; u4++) {
            xs[kb + u4 * 4 + 0][r] = vx[u4].x;
            xs[kb + u4 * 4 + 1][r] = vx[u4].y;
            xs[kb + u4 * 4 + 2][r] = vx[u4].z;
            xs[kb + u4 * 4 + 3][r] = vx[u4].w;
            ws[kb + u4 * 4 + 0][r] = vw[u4].x;
            ws[kb + u4 * 4 + 1][r] = vw[u4].y;
            ws[kb + u4 * 4 + 2][r] = vw[u4].z;
            ws[kb + u4 * 4 + 3][r] = vw[u4].w;
        }
        __syncthreads();
#pragma unroll
        for (int kk = 0; kk < 32; kk++) {
            float4 a0 = *(const float4*)&xs[kk][ty * 8];
            float4 a1 = *(const float4*)&xs[kk][ty * 8 + 4];
            float4 b0 = *(const float4*)&ws[kk][tx * 8];
            float4 b1 = *(const float4*)&ws[kk][tx * 8 + 4];
            float ra[8] = {a0.x, a0.y, a0.z, a0.w, a1.x, a1.y, a1.z, a1.w};
            float rb[8] = {b0.x, b0.y, b0.z, b0.w, b1.x, b1.y, b1.z, b1.w};
#pragma unroll
            for (int i = 0; i < 8; i++)
#pragma unroll
                for (int j = 0; j < 8; j++) acc[i][j] += ra[i] * rb[j];
        }
    }

    int c0 = tx * 8;
    float4 bl = *(const float4*)(bias + c0);
    float4 bh = *(const float4*)(bias + c0 + 4);
#pragma unroll
    for (int i = 0; i < 8; i++) {
        int grow = row0 + ty * 8 + i;
        if (grow < n) {
            float4 o0 = make_float4(acc[i][0] + bl.x, acc[i][1] + bl.y,
                                    acc[i][2] + bl.z, acc[i][3] + bl.w);
            float4 o1 = make_float4(acc[i][4] + bh.x, acc[i][5] + bh.y,
                                    acc[i][6] + bh.z, acc[i][7] + bh.w);
            *(float4*)(Z + (size_t)grow * D + c0)     = o0;
            *(float4*)(Z + (size_t)grow * D + c0 + 4) = o1;
        }
    }
}

// ---------------- attention projections: a_src/a_dst per node ---------------
__global__ void attn_proj_kernel(const float* __restrict__ z, const float* __restrict__ aW,
                                 float* __restrict__ asrc, float* __restrict__ adst, int n)
{
    int warp = (blockIdx.x * blockDim.x + threadIdx.x) >> 5;
    int lane = threadIdx.x & 31;
    if (warp >= n) return;
    float4 zv = *(const float4*)(z + (size_t)warp * D + lane * 4);
    float4 w1 = *(const float4*)(aW + lane * 4);
    float4 w2 = *(const float4*)(aW + D + lane * 4);
    float s1 = zv.x * w1.x + zv.y * w1.y + zv.z * w1.z + zv.w * w1.w;
    float s2 = zv.x * w2.x + zv.y * w2.y + zv.z * w2.z + zv.w * w2.w;
#pragma unroll
    for (int o = 16; o; o >>= 1) {
        s1 += __shfl_xor_sync(0xffffffffu, s1, o);
        s2 += __shfl_xor_sync(0xffffffffu, s2, o);
    }
    if (lane == 0) { asrc[warp] = s1; adst[warp] = s2; }
}

// ---------------- fused segment softmax + weighted gather ------------------
// One warp per dst node. Pass 1: online max+sum over incoming edges.
// Pass 2: alpha computed once per edge (lane-strided), broadcast via shfl,
// each lane accumulates 4 feature channels of sum(alpha * z[src]).
__global__ void aggregate_kernel(const float* __restrict__ z,
                                 const float* __restrict__ asrc,
                                 const float* __restrict__ adst,
                                 const int* __restrict__ off,
                                 const int* __restrict__ csr_src,
                                 const float* __restrict__ ab,
                                 float* __restrict__ out, int n)
{
    int warp = (blockIdx.x * blockDim.x + threadIdx.x) >> 5;
    int lane = threadIdx.x & 31;
    if (warp >= n) return;
    int beg = off[warp], end = off[warp + 1];
    float advv = adst[warp] + ab[0];

    // pass 1: online softmax statistics (finite identity avoids inf-inf NaN)
    float m = -1e30f, s = 0.f;
    for (int j = beg + lane; j < end; j += 32) {
        int sj = csr_src[j];
        float e = asrc[sj] + advv;
        e = (e > 0.f) ? e : 0.01f * e;
        if (e > m) { s = s * __expf(m - e) + 1.f; m = e; }
        else       { s += __expf(e - m); }
    }
#pragma unroll
    for (int o = 16; o; o >>= 1) {
        float m2 = __shfl_xor_sync(0xffffffffu, m, o);
        float s2 = __shfl_xor_sync(0xffffffffu, s, o);
        float mn = fmaxf(m, m2);
        s = s * __expf(m - mn) + s2 * __expf(m2 - mn);
        m = mn;
    }
    float inv_s = (end > beg) ? 1.f / s : 0.f;

    // pass 2: weighted gather
    float4 acc = make_float4(0.f, 0.f, 0.f, 0.f);
    for (int j0 = beg; j0 < end; j0 += 32) {
        int j = j0 + lane;
        float alpha = 0.f;
        int sj = 0;
        if (j < end) {
            sj = csr_src[j];
            float e = asrc[sj] + advv;
            e = (e > 0.f) ? e : 0.01f * e;
            alpha = __expf(e - m) * inv_s;
        }
        int cnt = min(32, end - j0);
        for (int t = 0; t < cnt; t++) {
            float a  = __shfl_sync(0xffffffffu, alpha, t);
            int   sn = __shfl_sync(0xffffffffu, sj, t);
            float4 zv = *(const float4*)(z + (size_t)sn * D + lane * 4);
            acc.x += a * zv.x;
            acc.y += a * zv.y;
            acc.z += a * zv.z;
            acc.w += a * zv.w;
        }
    }
    *(float4*)(out + (size_t)warp * D + lane * 4) = acc;
}

// ---------------- launch ----------------------------------------------------
extern "C" void kernel_launch(void* const* d_in, const int* in_sizes, int n_in,
                              void* d_out, int out_size)
{
    const float* x   = (const float*)d_in[0];
    const int*   src = (const int*)d_in[1];
    const int*   dst = (const int*)d_in[2];
    // d_in[3] = t (unused)
    const float* W[3]  = {(const float*)d_in[4],  (const float*)d_in[8],  (const float*)d_in[12]};
    const float* b[3]  = {(const float*)d_in[5],  (const float*)d_in[9],  (const float*)d_in[13]};
    const float* aW[3] = {(const float*)d_in[6],  (const float*)d_in[10], (const float*)d_in[14]};
    const float* ab[3] = {(const float*)d_in[7],  (const float*)d_in[11], (const float*)d_in[15]};

    int n = in_sizes[0] / D;   // 50000
    int E = in_sizes[1];       // 1600000

    float *z, *h, *asrc, *adst;
    int *deg, *cur, *off, *csr;
    cudaGetSymbolAddress((void**)&z,    g_z);
    cudaGetSymbolAddress((void**)&h,    g_h);
    cudaGetSymbolAddress((void**)&asrc, g_asrc);
    cudaGetSymbolAddress((void**)&adst, g_adst);
    cudaGetSymbolAddress((void**)&deg,  g_deg);
    cudaGetSymbolAddress((void**)&cur,  g_cur);
    cudaGetSymbolAddress((void**)&off,  g_off);
    cudaGetSymbolAddress((void**)&csr,  g_csr_src);

    float* outf = (float*)d_out;

    // ---- CSR build (once per launch; graph has fixed topology) ----
    {
        int tb = 256;
        zero_kernel<<<(n + tb - 1) / tb, tb>>>(deg, cur, n);
        hist_kernel<<<(E + tb - 1) / tb, tb>>>(dst, deg, E);
        scan_kernel<<<1, 1024>>>(deg, off, n);
        scatter_kernel<<<(E + tb - 1) / tb, tb>>>(src, dst, off, cur, csr, E);
    }

    int gemm_blocks = (n + 127) / 128;
    int warp_blocks = (n + 7) / 8;  // 256 threads = 8 warps, 1 warp/node

    // ---- layer 0: input x, no relu on load ----
    gemm_kernel<false><<<gemm_blocks, 256>>>(x, W[0], b[0], z, n);
    attn_proj_kernel<<<warp_blocks, 256>>>(z, aW[0], asrc, adst, n);
    aggregate_kernel<<<warp_blocks, 256>>>(z, asrc, adst, off, csr, ab[0], h, n);

    // ---- layer 1: relu(h) on load ----
    gemm_kernel<true><<<gemm_blocks, 256>>>(h, W[1], b[1], z, n);
    attn_proj_kernel<<<warp_blocks, 256>>>(z, aW[1], asrc, adst, n);
    aggregate_kernel<<<warp_blocks, 256>>>(z, asrc, adst, off, csr, ab[1], h, n);

    // ---- layer 2: relu(h) on load, write final output ----
    gemm_kernel<true><<<gemm_blocks, 256>>>(h, W[2], b[2], z, n);
    attn_proj_kernel<<<warp_blocks, 256>>>(z, aW[2], asrc, adst, n);
    aggregate_kernel<<<warp_blocks, 256>>>(z, asrc, adst, off, csr, ab[2], outf, n);
}

// round 2
// speedup vs baseline: 1.0162x; 1.0162x over previous
#include <cuda_runtime.h>
#include <cuda_fp16.h>
#include <cuda_bf16.h>

// Problem constants (fixed by the dataset)
#define N_NODES 50000
#define N_EDGES 1600000
#define D 128

// ---------------- scratch (device globals; no allocation allowed) ----------
__device__ __align__(16) __half g_z16[N_NODES * D];  // per-layer linear output (gather payload)
__device__ __align__(16) float  g_h[N_NODES * D];    // per-layer aggregated output
__device__ float g_asrc[N_NODES];
__device__ float g_adst[N_NODES];
__device__ int   g_deg[N_NODES];
__device__ int   g_cur[N_NODES];
__device__ int   g_off[N_NODES + 1];
__device__ int   g_csr_src[N_EDGES];    // src node id, grouped by dst

// ---------------- CSR build ------------------------------------------------
__global__ void zero_kernel(int* a, int* b, int n) {
    int i = blockIdx.x * blockDim.x + threadIdx.x;
    if (i < n) { a[i] = 0; b[i] = 0; }
}

__global__ void hist_kernel(const int* __restrict__ dst, int* __restrict__ deg, int E) {
    int i4 = (blockIdx.x * blockDim.x + threadIdx.x) * 4;
    if (i4 + 3 < E) {
        int4 v = *(const int4*)(dst + i4);
        atomicAdd(&deg[v.x], 1);
        atomicAdd(&deg[v.y], 1);
        atomicAdd(&deg[v.z], 1);
        atomicAdd(&deg[v.w], 1);
    } else {
        for (int i = i4; i < E; i++) atomicAdd(&deg[dst[i]], 1);
    }
}

// single-block exclusive scan: 1024 threads x 49 contiguous elems/thread
__global__ void scan_kernel(const int* __restrict__ deg, int* __restrict__ off, int n) {
    const int C = 49;  // 1024*49 = 50176 >= 50000
    __shared__ int wsum[32];
    int tid = threadIdx.x, lane = tid & 31, wid = tid >> 5;
    int base = tid * C;
    int s = 0;
    for (int u = 0; u < C; u++) {
        int i = base + u;
        if (i < n) s += deg[i];
    }
    int x = s;
#pragma unroll
    for (int o = 1; o < 32; o <<= 1) {
        int y = __shfl_up_sync(0xffffffffu, x, o);
        if (lane >= o) x += y;
    }
    if (lane == 31) wsum[wid] = x;
    __syncthreads();
    if (wid == 0) {
        int w = wsum[lane];
#pragma unroll
        for (int o = 1; o < 32; o <<= 1) {
            int y = __shfl_up_sync(0xffffffffu, w, o);
            if (lane >= o) w += y;
        }
        wsum[lane] = w;
    }
    __syncthreads();
    int run = x - s + (wid ? wsum[wid - 1] : 0);
    for (int u = 0; u < C; u++) {
        int i = base + u;
        if (i < n) { off[i] = run; run += deg[i]; }
    }
    if (tid == 1023) off[n] = run;
}

__global__ void scatter_kernel(const int* __restrict__ src, const int* __restrict__ dst,
                               const int* __restrict__ off, int* __restrict__ cur,
                               int* __restrict__ csr_src, int E) {
    int i = blockIdx.x * blockDim.x + threadIdx.x;
    if (i >= E) return;
    int d = dst[i];
    int p = off[d] + atomicAdd(&cur[d], 1);
    csr_src[p] = src[i];
}

// ---------------- GEMM + fused attention projections ------------------------
// Z16 = fp16(act(X) @ W^T + b); asrc/adst = Z @ aW halves, computed from the
// fp32 register accumulators (full precision) and reduced across the 16
// column-owning threads per row via half-warp shfl.
template <bool RELU>
__global__ __launch_bounds__(256) void gemm_kernel(
    const float* __restrict__ X, const float* __restrict__ W,
    const float* __restrict__ bias, const float* __restrict__ aW,
    __half* __restrict__ Z16, float* __restrict__ asrc, float* __restrict__ adst, int n)
{
    __shared__ float xs[32][128];
    __shared__ float ws[32][128];
    int tid = threadIdx.x;
    int tx = tid & 15, ty = tid >> 4;
    int row0 = blockIdx.x * 128;
    int r  = tid & 127;          // row (X) / out (W) index inside tile
    int kb = (tid >> 7) * 16;    // 16-wide k slab

    float acc[8][8];
#pragma unroll
    for (int i = 0; i < 8; i++)
#pragma unroll
        for (int j = 0; j < 8; j++) acc[i][j] = 0.f;

    for (int k0 = 0; k0 < 128; k0 += 32) {
        float4 vx[4], vw[4];
        int grow = row0 + r;
        bool xok = grow < n;
#pragma unroll
        for (int u4 = 0; u4 < 4; u4++) {
            vx[u4] = xok ? *(const float4*)(X + (size_t)grow * D + k0 + kb + u4 * 4)
                         : make_float4(0.f, 0.f, 0.f, 0.f);
            vw[u4] = *(const float4*)(W + (size_t)r * D + k0 + kb + u4 * 4);
            if (RELU) {
                vx[u4].x = fmaxf(vx[u4].x, 0.f);
                vx[u4].y = fmaxf(vx[u4].y, 0.f);
                vx[u4].z = fmaxf(vx[u4].z, 0.f);
                vx[u4].w = fmaxf(vx[u4].w, 0.f);
            }
        }
        __syncthreads();  // protect previous compute before overwrite
#pragma unroll
        for (int u4 = 0; u4 < 4; u4++) {
            xs[kb + u4 * 4 + 0][r] = vx[u4].x;
            xs[kb + u4 * 4 + 1][r] = vx[u4].y;
            xs[kb + u4 * 4 + 2][r] = vx[u4].z;
            xs[kb + u4 * 4 + 3][r] = vx[u4].w;
            ws[kb + u4 * 4 + 0][r] = vw[u4].x;
            ws[kb + u4 * 4 + 1][r] = vw[u4].y;
            ws[kb + u4 * 4 + 2][r] = vw[u4].z;
            ws[kb + u4 * 4 + 3][r] = vw[u4].w;
        }
        __syncthreads();
#pragma unroll
        for (int kk = 0; kk < 32; kk++) {
            float4 a0 = *(const float4*)&xs[kk][ty * 8];
            float4 a1 = *(const float4*)&xs[kk][ty * 8 + 4];
            float4 b0 = *(const float4*)&ws[kk][tx * 8];
            float4 b1 = *(const float4*)&ws[kk][tx * 8 + 4];
            float ra[8] = {a0.x, a0.y, a0.z, a0.w, a1.x, a1.y, a1.z, a1.w};
            float rb[8] = {b0.x, b0.y, b0.z, b0.w, b1.x, b1.y, b1.z, b1.w};
#pragma unroll
            for (int i = 0; i < 8; i++)
#pragma unroll
                for (int j = 0; j < 8; j++) acc[i][j] += ra[i] * rb[j];
        }
    }

    int c0 = tx * 8;
    float4 bl = *(const float4*)(bias + c0);
    float4 bh = *(const float4*)(bias + c0 + 4);
    float aw1[8], aw2[8];
    {
        float4 t0 = *(const float4*)(aW + c0);
        float4 t1 = *(const float4*)(aW + c0 + 4);
        float4 t2 = *(const float4*)(aW + D + c0);
        float4 t3 = *(const float4*)(aW + D + c0 + 4);
        aw1[0]=t0.x; aw1[1]=t0.y; aw1[2]=t0.z; aw1[3]=t0.w;
        aw1[4]=t1.x; aw1[5]=t1.y; aw1[6]=t1.z; aw1[7]=t1.w;
        aw2[0]=t2.x; aw2[1]=t2.y; aw2[2]=t2.z; aw2[3]=t2.w;
        aw2[4]=t3.x; aw2[5]=t3.y; aw2[6]=t3.z; aw2[7]=t3.w;
    }
    float bb[8] = {bl.x, bl.y, bl.z, bl.w, bh.x, bh.y, bh.z, bh.w};

#pragma unroll
    for (int i = 0; i < 8; i++) {
        int grow = row0 + ty * 8 + i;
        float o[8];
        float p1 = 0.f, p2 = 0.f;
#pragma unroll
        for (int j = 0; j < 8; j++) {
            o[j] = acc[i][j] + bb[j];
            p1 += o[j] * aw1[j];
            p2 += o[j] * aw2[j];
        }
        // reduce p1/p2 across the 16 threads (same ty) covering this row
#pragma unroll
        for (int m = 8; m; m >>= 1) {
            p1 += __shfl_xor_sync(0xffffffffu, p1, m);
            p2 += __shfl_xor_sync(0xffffffffu, p2, m);
        }
        if (grow < n) {
            __half2 q0 = __floats2half2_rn(o[0], o[1]);
            __half2 q1 = __floats2half2_rn(o[2], o[3]);
            __half2 q2 = __floats2half2_rn(o[4], o[5]);
            __half2 q3 = __floats2half2_rn(o[6], o[7]);
            uint4 u;
            u.x = *reinterpret_cast<unsigned*>(&q0);
            u.y = *reinterpret_cast<unsigned*>(&q1);
            u.z = *reinterpret_cast<unsigned*>(&q2);
            u.w = *reinterpret_cast<unsigned*>(&q3);
            *(uint4*)(Z16 + (size_t)grow * D + c0) = u;
            if (tx == 0) { asrc[grow] = p1; adst[grow] = p2; }
        }
    }
}

// ---------------- fused segment softmax + weighted gather ------------------
// One warp per dst node. Pass 1: online max+sum over incoming edges.
// Pass 2: alpha computed once per edge (lane-strided), broadcast via shfl;
// each lane accumulates 4 feature channels from the fp16 z row (8B/lane,
// 256B coalesced per edge).
__global__ void aggregate_kernel(const __half* __restrict__ z16,
                                 const float* __restrict__ asrc,
                                 const float* __restrict__ adst,
                                 const int* __restrict__ off,
                                 const int* __restrict__ csr_src,
                                 const float* __restrict__ ab,
                                 float* __restrict__ out, int n)
{
    int warp = (blockIdx.x * blockDim.x + threadIdx.x) >> 5;
    int lane = threadIdx.x & 31;
    if (warp >= n) return;
    int beg = off[warp], end = off[warp + 1];
    float advv = adst[warp] + ab[0];

    // pass 1: online softmax statistics (finite identity avoids inf-inf NaN)
    float m = -1e30f, s = 0.f;
    for (int j = beg + lane; j < end; j += 32) {
        int sj = csr_src[j];
        float e = asrc[sj] + advv;
        e = (e > 0.f) ? e : 0.01f * e;
        if (e > m) { s = s * __expf(m - e) + 1.f; m = e; }
        else       { s += __expf(e - m); }
    }
#pragma unroll
    for (int o = 16; o; o >>= 1) {
        float m2 = __shfl_xor_sync(0xffffffffu, m, o);
        float s2 = __shfl_xor_sync(0xffffffffu, s, o);
        float mn = fmaxf(m, m2);
        s = s * __expf(m - mn) + s2 * __expf(m2 - mn);
        m = mn;
    }
    float inv_s = (end > beg) ? 1.f / s : 0.f;

    // pass 2: weighted gather (fp16 payload)
    float4 acc = make_float4(0.f, 0.f, 0.f, 0.f);
    for (int j0 = beg; j0 < end; j0 += 32) {
        int j = j0 + lane;
        float alpha = 0.f;
        int sj = 0;
        if (j < end) {
            sj = csr_src[j];
            float e = asrc[sj] + advv;
            e = (e > 0.f) ? e : 0.01f * e;
            alpha = __expf(e - m) * inv_s;
        }
        int cnt = min(32, end - j0);
        for (int t = 0; t < cnt; t++) {
            float a  = __shfl_sync(0xffffffffu, alpha, t);
            int   sn = __shfl_sync(0xffffffffu, sj, t);
            uint2 raw = *(const uint2*)(z16 + (size_t)sn * D + lane * 4);
            __half2 h0 = *reinterpret_cast<__half2*>(&raw.x);
            __half2 h1 = *reinterpret_cast<__half2*>(&raw.y);
            float2 f0 = __half22float2(h0);
            float2 f1 = __half22float2(h1);
            acc.x += a * f0.x;
            acc.y += a * f0.y;
            acc.z += a * f1.x;
            acc.w += a * f1.y;
        }
    }
    *(float4*)(out + (size_t)warp * D + lane * 4) = acc;
}

// ---------------- launch ----------------------------------------------------
extern "C" void kernel_launch(void* const* d_in, const int* in_sizes, int n_in,
                              void* d_out, int out_size)
{
    const float* x   = (const float*)d_in[0];
    const int*   src = (const int*)d_in[1];
    const int*   dst = (const int*)d_in[2];
    // d_in[3] = t (unused)
    const float* W[3]  = {(const float*)d_in[4],  (const float*)d_in[8],  (const float*)d_in[12]};
    const float* b[3]  = {(const float*)d_in[5],  (const float*)d_in[9],  (const float*)d_in[13]};
    const float* aW[3] = {(const float*)d_in[6],  (const float*)d_in[10], (const float*)d_in[14]};
    const float* ab[3] = {(const float*)d_in[7],  (const float*)d_in[11], (const float*)d_in[15]};

    int n = in_sizes[0] / D;   // 50000
    int E = in_sizes[1];       // 1600000

    __half* z16;
    float *h, *asrc, *adst;
    int *deg, *cur, *off, *csr;
    cudaGetSymbolAddress((void**)&z16,  g_z16);
    cudaGetSymbolAddress((void**)&h,    g_h);
    cudaGetSymbolAddress((void**)&asrc, g_asrc);
    cudaGetSymbolAddress((void**)&adst, g_adst);
    cudaGetSymbolAddress((void**)&deg,  g_deg);
    cudaGetSymbolAddress((void**)&cur,  g_cur);
    cudaGetSymbolAddress((void**)&off,  g_off);
    cudaGetSymbolAddress((void**)&csr,  g_csr_src);

    float* outf = (float*)d_out;

    // ---- CSR build (once per launch; graph has fixed topology) ----
    {
        int tb = 256;
        zero_kernel<<<(n + tb - 1) / tb, tb>>>(deg, cur, n);
        hist_kernel<<<(E / 4 + tb - 1) / tb, tb>>>(dst, deg, E);
        scan_kernel<<<1, 1024>>>(deg, off, n);
        scatter_kernel<<<(E + tb - 1) / tb, tb>>>(src, dst, off, cur, csr, E);
    }

    int gemm_blocks = (n + 127) / 128;
    int warp_blocks = (n + 7) / 8;  // 256 threads = 8 warps, 1 warp/node

    // ---- layer 0: input x, no relu on load ----
    gemm_kernel<false><<<gemm_blocks, 256>>>(x, W[0], b[0], aW[0], z16, asrc, adst, n);
    aggregate_kernel<<<warp_blocks, 256>>>(z16, asrc, adst, off, csr, ab[0], h, n);

    // ---- layer 1: relu(h) on load ----
    gemm_kernel<true><<<gemm_blocks, 256>>>(h, W[1], b[1], aW[1], z16, asrc, adst, n);
    aggregate_kernel<<<warp_blocks, 256>>>(z16, asrc, adst, off, csr, ab[1], h, n);

    // ---- layer 2: relu(h) on load, write final output ----
    gemm_kernel<true><<<gemm_blocks, 256>>>(h, W[2], b[2], aW[2], z16, asrc, adst, n);
    aggregate_kernel<<<warp_blocks, 256>>>(z16, asrc, adst, off, csr, ab[2], outf, n);
}

// round 6
// speedup vs baseline: 1.2447x; 1.2248x over previous
#include <cuda_runtime.h>
#include <cuda_fp16.h>
#include <mma.h>

using namespace nvcuda;

// Problem constants (fixed by the dataset)
#define N_NODES 50000
#define N_EDGES 1600000
#define D 128

// ---------------- scratch (device globals; no allocation allowed) ----------
__device__ __align__(16) __half g_x16[N_NODES * D];  // fp16 GEMM input
__device__ __align__(16) __half g_z16[N_NODES * D];  // fp16 GEMM output / gather payload
__device__ __align__(16) __half g_w16[3 * D * D];    // fp16 weights
__device__ __align__(16) float  g_h[N_NODES * D];    // fp32 aggregated output
__device__ float g_asrc[N_NODES];
__device__ float g_adst[N_NODES];
__device__ int   g_deg[N_NODES];
__device__ int   g_cur[N_NODES];
__device__ int   g_off[N_NODES + 1];
__device__ int   g_csr_src[N_EDGES];

// ---------------- CSR build ------------------------------------------------
__global__ void zero_kernel(int* a, int* b, int n) {
    int i = blockIdx.x * blockDim.x + threadIdx.x;
    if (i < n) { a[i] = 0; b[i] = 0; }
}

__global__ void hist_kernel(const int* __restrict__ dst, int* __restrict__ deg, int E) {
    int i4 = (blockIdx.x * blockDim.x + threadIdx.x) * 4;
    if (i4 + 3 < E) {
        int4 v = *(const int4*)(dst + i4);
        atomicAdd(&deg[v.x], 1);
        atomicAdd(&deg[v.y], 1);
        atomicAdd(&deg[v.z], 1);
        atomicAdd(&deg[v.w], 1);
    } else {
        for (int i = i4; i < E; i++) atomicAdd(&deg[dst[i]], 1);
    }
}

// single-block exclusive scan: 1024 threads x 49 contiguous elems/thread
__global__ void scan_kernel(const int* __restrict__ deg, int* __restrict__ off, int n) {
    const int C = 49;  // 1024*49 = 50176 >= 50000
    __shared__ int wsum[32];
    int tid = threadIdx.x, lane = tid & 31, wid = tid >> 5;
    int base = tid * C;
    int s = 0;
    for (int u = 0; u < C; u++) {
        int i = base + u;
        if (i < n) s += deg[i];
    }
    int x = s;
#pragma unroll
    for (int o = 1; o < 32; o <<= 1) {
        int y = __shfl_up_sync(0xffffffffu, x, o);
        if (lane >= o) x += y;
    }
    if (lane == 31) wsum[wid] = x;
    __syncthreads();
    if (wid == 0) {
        int w = wsum[lane];
#pragma unroll
        for (int o = 1; o < 32; o <<= 1) {
            int y = __shfl_up_sync(0xffffffffu, w, o);
            if (lane >= o) w += y;
        }
        wsum[lane] = w;
    }
    __syncthreads();
    int run = x - s + (wid ? wsum[wid - 1] : 0);
    for (int u = 0; u < C; u++) {
        int i = base + u;
        if (i < n) { off[i] = run; run += deg[i]; }
    }
    if (tid == 1023) off[n] = run;
}

__global__ void scatter_kernel(const int* __restrict__ src, const int* __restrict__ dst,
                               const int* __restrict__ off, int* __restrict__ cur,
                               int* __restrict__ csr_src, int E) {
    int i = blockIdx.x * blockDim.x + threadIdx.x;
    if (i >= E) return;
    int d = dst[i];
    int p = off[d] + atomicAdd(&cur[d], 1);
    csr_src[p] = src[i];
}

// ---------------- fp32 -> fp16 conversion (optional relu) -------------------
__global__ void cvt_f2h_kernel(const float* __restrict__ in, __half* __restrict__ out16,
                               int n8, int do_relu) {
    int i = blockIdx.x * blockDim.x + threadIdx.x;
    if (i >= n8) return;
    const float4* p = (const float4*)in + (size_t)i * 2;
    float4 a = p[0], b = p[1];
    if (do_relu) {
        a.x = fmaxf(a.x, 0.f); a.y = fmaxf(a.y, 0.f);
        a.z = fmaxf(a.z, 0.f); a.w = fmaxf(a.w, 0.f);
        b.x = fmaxf(b.x, 0.f); b.y = fmaxf(b.y, 0.f);
        b.z = fmaxf(b.z, 0.f); b.w = fmaxf(b.w, 0.f);
    }
    __half2 h0 = __floats2half2_rn(a.x, a.y);
    __half2 h1 = __floats2half2_rn(a.z, a.w);
    __half2 h2 = __floats2half2_rn(b.x, b.y);
    __half2 h3 = __floats2half2_rn(b.z, b.w);
    uint4 u;
    u.x = *reinterpret_cast<unsigned*>(&h0);
    u.y = *reinterpret_cast<unsigned*>(&h1);
    u.z = *reinterpret_cast<unsigned*>(&h2);
    u.w = *reinterpret_cast<unsigned*>(&h3);
    *((uint4*)out16 + i) = u;
}

// ---------------- WMMA GEMM + fused attention projections -------------------
// Z16 = fp16(X16 @ W16^T + b); asrc/adst = Z @ aW halves from fp32 accums.
// Block: 128 rows, full N=128, full K=128 staged once. 8 warps, 16 rows each,
// 8 accumulator fragments per warp. Padded ld=136 halves for staging tiles.
// W is [n][k] row-major; as a col_major wmma matrix_b with ld=136 this gives
// B(k,n) = W[n][k] exactly.
#define LDP 136
#define GEMM_SMEM_BYTES (2 * 128 * LDP * 2)   // 69632; also covers 128*128*4 float C

__global__ __launch_bounds__(256) void gemm_kernel(
    const __half* __restrict__ X16, const __half* __restrict__ W16,
    const float* __restrict__ bias, const float* __restrict__ aW,
    __half* __restrict__ Z16, float* __restrict__ asrc, float* __restrict__ adst, int n)
{
    extern __shared__ __half smbuf[];
    __half* As = smbuf;                  // [128][LDP]
    __half* Ws = smbuf + 128 * LDP;      // [128][LDP]
    int tid = threadIdx.x;
    int row0 = blockIdx.x * 128;

    // stage X tile (zero-filled past n) and W, 8 x 16B chunks per thread each
    for (int i = 0; i < 8; i++) {
        int c = tid + i * 256;           // 0..2047
        int row = c >> 4;
        int k8 = c & 15;
        uint4 v = make_uint4(0u, 0u, 0u, 0u);
        int grow = row0 + row;
        if (grow < n) v = *(const uint4*)(X16 + (size_t)grow * D + k8 * 8);
        *(uint4*)(As + row * LDP + k8 * 8) = v;
        uint4 wv = *(const uint4*)(W16 + row * D + k8 * 8);
        *(uint4*)(Ws + row * LDP + k8 * 8) = wv;
    }
    __syncthreads();

    int warp = tid >> 5;
    wmma::fragment<wmma::accumulator, 16, 16, 16, float> cfrag[8];
    for (int j = 0; j < 8; j++) wmma::fill_fragment(cfrag[j], 0.0f);

    for (int k = 0; k < 8; k++) {
        wmma::fragment<wmma::matrix_a, 16, 16, 16, __half, wmma::row_major> afrag;
        wmma::load_matrix_sync(afrag, As + (warp * 16) * LDP + k * 16, LDP);
        for (int j = 0; j < 8; j++) {
            wmma::fragment<wmma::matrix_b, 16, 16, 16, __half, wmma::col_major> bfrag;
            wmma::load_matrix_sync(bfrag, Ws + (j * 16) * LDP + k * 16, LDP);
            wmma::mma_sync(cfrag[j], afrag, bfrag, cfrag[j]);
        }
    }
    __syncthreads();   // tiles dead; reuse smem for the fp32 C buffer

    float* Cs = (float*)smbuf;           // [128][128]
    for (int j = 0; j < 8; j++)
        wmma::store_matrix_sync(Cs + (warp * 16) * 128 + j * 16, cfrag[j], 128,
                                wmma::mem_row_major);
    __syncthreads();

    // epilogue: thread t handles row t/2, 64 channels; pair-reduce projections
    int row = tid >> 1;
    int hh = tid & 1;
    int c0 = hh * 64;
    int grow = row0 + row;
    float p1 = 0.f, p2 = 0.f;
    __half2 hv[32];
    for (int j = 0; j < 32; j++) {
        float ox = Cs[row * 128 + c0 + 2 * j]     + bias[c0 + 2 * j];
        float oy = Cs[row * 128 + c0 + 2 * j + 1] + bias[c0 + 2 * j + 1];
        p1 += ox * aW[c0 + 2 * j]     + oy * aW[c0 + 2 * j + 1];
        p2 += ox * aW[D + c0 + 2 * j] + oy * aW[D + c0 + 2 * j + 1];
        hv[j] = __floats2half2_rn(ox, oy);
    }
    p1 += __shfl_xor_sync(0xffffffffu, p1, 1);
    p2 += __shfl_xor_sync(0xffffffffu, p2, 1);
    if (grow < n) {
        uint4* dst4 = (uint4*)(Z16 + (size_t)grow * D + c0);
        const uint4* src4 = (const uint4*)hv;
        for (int j = 0; j < 8; j++) dst4[j] = src4[j];
        if (hh == 0) { asrc[grow] = p1; adst[grow] = p2; }
    }
}

// ---------------- fused segment softmax + weighted gather ------------------
// One warp per dst node. Pass 1: online max+sum over incoming edges.
// Pass 2: alpha computed once per edge (lane-strided), broadcast via shfl;
// each lane accumulates 4 feature channels from the fp16 z row.
__global__ void aggregate_kernel(const __half* __restrict__ z16,
                                 const float* __restrict__ asrc,
                                 const float* __restrict__ adst,
                                 const int* __restrict__ off,
                                 const int* __restrict__ csr_src,
                                 const float* __restrict__ ab,
                                 float* __restrict__ out, int n)
{
    int warp = (blockIdx.x * blockDim.x + threadIdx.x) >> 5;
    int lane = threadIdx.x & 31;
    if (warp >= n) return;
    int beg = off[warp], end = off[warp + 1];
    float advv = adst[warp] + ab[0];

    // pass 1: online softmax statistics (finite identity avoids inf-inf NaN)
    float m = -1e30f, s = 0.f;
    for (int j = beg + lane; j < end; j += 32) {
        int sj = csr_src[j];
        float e = asrc[sj] + advv;
        e = (e > 0.f) ? e : 0.01f * e;
        if (e > m) { s = s * __expf(m - e) + 1.f; m = e; }
        else       { s += __expf(e - m); }
    }
#pragma unroll
    for (int o = 16; o; o >>= 1) {
        float m2 = __shfl_xor_sync(0xffffffffu, m, o);
        float s2 = __shfl_xor_sync(0xffffffffu, s, o);
        float mn = fmaxf(m, m2);
        s = s * __expf(m - mn) + s2 * __expf(m2 - mn);
        m = mn;
    }
    float inv_s = (end > beg) ? 1.f / s : 0.f;

    // pass 2: weighted gather (fp16 payload)
    float4 acc = make_float4(0.f, 0.f, 0.f, 0.f);
    for (int j0 = beg; j0 < end; j0 += 32) {
        int j = j0 + lane;
        float alpha = 0.f;
        int sj = 0;
        if (j < end) {
            sj = csr_src[j];
            float e = asrc[sj] + advv;
            e = (e > 0.f) ? e : 0.01f * e;
            alpha = __expf(e - m) * inv_s;
        }
        int cnt = min(32, end - j0);
        for (int t = 0; t < cnt; t++) {
            float a  = __shfl_sync(0xffffffffu, alpha, t);
            int   sn = __shfl_sync(0xffffffffu, sj, t);
            uint2 raw = *(const uint2*)(z16 + (size_t)sn * D + lane * 4);
            __half2 h0 = *reinterpret_cast<__half2*>(&raw.x);
            __half2 h1 = *reinterpret_cast<__half2*>(&raw.y);
            float2 f0 = __half22float2(h0);
            float2 f1 = __half22float2(h1);
            acc.x += a * f0.x;
            acc.y += a * f0.y;
            acc.z += a * f1.x;
            acc.w += a * f1.y;
        }
    }
    *(float4*)(out + (size_t)warp * D + lane * 4) = acc;
}

// ---------------- launch ----------------------------------------------------
extern "C" void kernel_launch(void* const* d_in, const int* in_sizes, int n_in,
                              void* d_out, int out_size)
{
    const float* x   = (const float*)d_in[0];
    const int*   src = (const int*)d_in[1];
    const int*   dst = (const int*)d_in[2];
    // d_in[3] = t (unused)
    const float* W0  = (const float*)d_in[4];
    const float* b0  = (const float*)d_in[5];
    const float* aW0 = (const float*)d_in[6];
    const float* ab0 = (const float*)d_in[7];
    const float* W1  = (const float*)d_in[8];
    const float* b1  = (const float*)d_in[9];
    const float* aW1 = (const float*)d_in[10];
    const float* ab1 = (const float*)d_in[11];
    const float* W2  = (const float*)d_in[12];
    const float* b2  = (const float*)d_in[13];
    const float* aW2 = (const float*)d_in[14];
    const float* ab2 = (const float*)d_in[15];

    int n = in_sizes[0] / D;   // 50000
    int E = in_sizes[1];       // 1600000

    __half *x16, *z16, *w16;
    float *h, *asrc, *adst;
    int *deg, *cur, *off, *csr;
    cudaGetSymbolAddress((void**)&x16,  g_x16);
    cudaGetSymbolAddress((void**)&z16,  g_z16);
    cudaGetSymbolAddress((void**)&w16,  g_w16);
    cudaGetSymbolAddress((void**)&h,    g_h);
    cudaGetSymbolAddress((void**)&asrc, g_asrc);
    cudaGetSymbolAddress((void**)&adst, g_adst);
    cudaGetSymbolAddress((void**)&deg,  g_deg);
    cudaGetSymbolAddress((void**)&cur,  g_cur);
    cudaGetSymbolAddress((void**)&off,  g_off);
    cudaGetSymbolAddress((void**)&csr,  g_csr_src);

    float* outf = (float*)d_out;

    // idempotent, host-side, not a stream op (safe under graph capture)
    cudaFuncSetAttribute(gemm_kernel, cudaFuncAttributeMaxDynamicSharedMemorySize,
                         GEMM_SMEM_BYTES);

    int tb = 256;
    // ---- CSR build ----
    zero_kernel<<<(n + tb - 1) / tb, tb>>>(deg, cur, n);
    hist_kernel<<<(E / 4 + tb - 1) / tb, tb>>>(dst, deg, E);
    scan_kernel<<<1, 1024>>>(deg, off, n);
    scatter_kernel<<<(E + tb - 1) / tb, tb>>>(src, dst, off, cur, csr, E);

    // ---- conversions: x and the three weight matrices to fp16 ----
    int n8x = n * D / 8;
    cvt_f2h_kernel<<<(n8x + tb - 1) / tb, tb>>>(x, x16, n8x, 0);
    cvt_f2h_kernel<<<(2048 + tb - 1) / tb, tb>>>(W0, w16,             2048, 0);
    cvt_f2h_kernel<<<(2048 + tb - 1) / tb, tb>>>(W1, w16 + D * D,     2048, 0);
    cvt_f2h_kernel<<<(2048 + tb - 1) / tb, tb>>>(W2, w16 + 2 * D * D, 2048, 0);

    int gemm_blocks = (n + 127) / 128;
    int warp_blocks = (n + 7) / 8;

    // ---- layer 0 ----
    gemm_kernel<<<gemm_blocks, 256, GEMM_SMEM_BYTES>>>(x16, w16, b0, aW0, z16, asrc, adst, n);
    aggregate_kernel<<<warp_blocks, 256>>>(z16, asrc, adst, off, csr, ab0, h, n);
    cvt_f2h_kernel<<<(n8x + tb - 1) / tb, tb>>>(h, x16, n8x, 1);
    // ---- layer 1 ----
    gemm_kernel<<<gemm_blocks, 256, GEMM_SMEM_BYTES>>>(x16, w16 + D * D, b1, aW1, z16, asrc, adst, n);
    aggregate_kernel<<<warp_blocks, 256>>>(z16, asrc, adst, off, csr, ab1, h, n);
    cvt_f2h_kernel<<<(n8x + tb - 1) / tb, tb>>>(h, x16, n8x, 1);
    // ---- layer 2 (fp32 out) ----
    gemm_kernel<<<gemm_blocks, 256, GEMM_SMEM_BYTES>>>(x16, w16 + 2 * D * D, b2, aW2, z16, asrc, adst, n);
    aggregate_kernel<<<warp_blocks, 256>>>(z16, asrc, adst, off, csr, ab2, outf, n);
}

// round 7
// speedup vs baseline: 1.3551x; 1.0888x over previous
#include <cuda_runtime.h>
#include <cuda_fp16.h>
#include <mma.h>

using namespace nvcuda;

// Problem constants (fixed by the dataset)
#define N_NODES 50000
#define N_EDGES 1600000
#define D 128

// ---------------- scratch (device globals; no allocation allowed) ----------
__device__ __align__(16) __half g_x16[N_NODES * D];  // fp16 GEMM input
__device__ __align__(16) __half g_z16[N_NODES * D];  // fp16 GEMM output / gather payload
__device__ __align__(16) __half g_w16[3 * D * D];    // fp16 weights
__device__ float g_asrc[N_NODES];
__device__ float g_adst[N_NODES];
__device__ int   g_deg[N_NODES];
__device__ int   g_cur[N_NODES];
__device__ int   g_off[N_NODES + 1];
__device__ int   g_csr_src[N_EDGES];

// ---------------- CSR build ------------------------------------------------
__global__ void zero_kernel(int* a, int* b, int n) {
    int i = blockIdx.x * blockDim.x + threadIdx.x;
    if (i < n) { a[i] = 0; b[i] = 0; }
}

__global__ void hist_kernel(const int* __restrict__ dst, int* __restrict__ deg, int E) {
    int i4 = (blockIdx.x * blockDim.x + threadIdx.x) * 4;
    if (i4 + 3 < E) {
        int4 v = *(const int4*)(dst + i4);
        atomicAdd(&deg[v.x], 1);
        atomicAdd(&deg[v.y], 1);
        atomicAdd(&deg[v.z], 1);
        atomicAdd(&deg[v.w], 1);
    } else {
        for (int i = i4; i < E; i++) atomicAdd(&deg[dst[i]], 1);
    }
}

// single-block exclusive scan: 1024 threads x 49 contiguous elems/thread
__global__ void scan_kernel(const int* __restrict__ deg, int* __restrict__ off, int n) {
    const int C = 49;  // 1024*49 = 50176 >= 50000
    __shared__ int wsum[32];
    int tid = threadIdx.x, lane = tid & 31, wid = tid >> 5;
    int base = tid * C;
    int s = 0;
    for (int u = 0; u < C; u++) {
        int i = base + u;
        if (i < n) s += deg[i];
    }
    int x = s;
#pragma unroll
    for (int o = 1; o < 32; o <<= 1) {
        int y = __shfl_up_sync(0xffffffffu, x, o);
        if (lane >= o) x += y;
    }
    if (lane == 31) wsum[wid] = x;
    __syncthreads();
    if (wid == 0) {
        int w = wsum[lane];
#pragma unroll
        for (int o = 1; o < 32; o <<= 1) {
            int y = __shfl_up_sync(0xffffffffu, w, o);
            if (lane >= o) w += y;
        }
        wsum[lane] = w;
    }
    __syncthreads();
    int run = x - s + (wid ? wsum[wid - 1] : 0);
    for (int u = 0; u < C; u++) {
        int i = base + u;
        if (i < n) { off[i] = run; run += deg[i]; }
    }
    if (tid == 1023) off[n] = run;
}

__global__ void scatter_kernel(const int* __restrict__ src, const int* __restrict__ dst,
                               const int* __restrict__ off, int* __restrict__ cur,
                               int* __restrict__ csr_src, int E) {
    int i = blockIdx.x * blockDim.x + threadIdx.x;
    if (i >= E) return;
    int d = dst[i];
    int p = off[d] + atomicAdd(&cur[d], 1);
    csr_src[p] = src[i];
}

// ---------------- fp32 -> fp16 conversion -----------------------------------
__global__ void cvt_f2h_kernel(const float* __restrict__ in, __half* __restrict__ out16,
                               int n8) {
    int i = blockIdx.x * blockDim.x + threadIdx.x;
    if (i >= n8) return;
    const float4* p = (const float4*)in + (size_t)i * 2;
    float4 a = p[0], b = p[1];
    __half2 h0 = __floats2half2_rn(a.x, a.y);
    __half2 h1 = __floats2half2_rn(a.z, a.w);
    __half2 h2 = __floats2half2_rn(b.x, b.y);
    __half2 h3 = __floats2half2_rn(b.z, b.w);
    uint4 u;
    u.x = *reinterpret_cast<unsigned*>(&h0);
    u.y = *reinterpret_cast<unsigned*>(&h1);
    u.z = *reinterpret_cast<unsigned*>(&h2);
    u.w = *reinterpret_cast<unsigned*>(&h3);
    *((uint4*)out16 + i) = u;
}

// ---------------- WMMA GEMM + fused attention projections -------------------
// Z16 = fp16(X16 @ W16^T + b); asrc/adst = Z @ aW halves from fp32 accums.
// Block: 128 rows, full N=128, full K=128 staged once. 8 warps, 16 rows each,
// 8 accumulator fragments per warp. Padded ld=136 halves for staging tiles.
// W is [n][k] row-major; as a col_major wmma matrix_b with ld this gives
// B(k,n) = W[n][k] exactly.
#define LDP 136
#define GEMM_SMEM_BYTES (2 * 128 * LDP * 2)   // 69632; also covers 128*128*4 float C

__global__ __launch_bounds__(256) void gemm_kernel(
    const __half* __restrict__ X16, const __half* __restrict__ W16,
    const float* __restrict__ bias, const float* __restrict__ aW,
    __half* __restrict__ Z16, float* __restrict__ asrc, float* __restrict__ adst, int n)
{
    extern __shared__ __half smbuf[];
    __half* As = smbuf;                  // [128][LDP]
    __half* Ws = smbuf + 128 * LDP;      // [128][LDP]
    int tid = threadIdx.x;
    int row0 = blockIdx.x * 128;

    // stage X tile (zero-filled past n) and W, 8 x 16B chunks per thread each
    for (int i = 0; i < 8; i++) {
        int c = tid + i * 256;           // 0..2047
        int row = c >> 4;
        int k8 = c & 15;
        uint4 v = make_uint4(0u, 0u, 0u, 0u);
        int grow = row0 + row;
        if (grow < n) v = *(const uint4*)(X16 + (size_t)grow * D + k8 * 8);
        *(uint4*)(As + row * LDP + k8 * 8) = v;
        uint4 wv = *(const uint4*)(W16 + row * D + k8 * 8);
        *(uint4*)(Ws + row * LDP + k8 * 8) = wv;
    }
    __syncthreads();

    int warp = tid >> 5;
    wmma::fragment<wmma::accumulator, 16, 16, 16, float> cfrag[8];
    for (int j = 0; j < 8; j++) wmma::fill_fragment(cfrag[j], 0.0f);

    for (int k = 0; k < 8; k++) {
        wmma::fragment<wmma::matrix_a, 16, 16, 16, __half, wmma::row_major> afrag;
        wmma::load_matrix_sync(afrag, As + (warp * 16) * LDP + k * 16, LDP);
        for (int j = 0; j < 8; j++) {
            wmma::fragment<wmma::matrix_b, 16, 16, 16, __half, wmma::col_major> bfrag;
            wmma::load_matrix_sync(bfrag, Ws + (j * 16) * LDP + k * 16, LDP);
            wmma::mma_sync(cfrag[j], afrag, bfrag, cfrag[j]);
        }
    }
    __syncthreads();   // tiles dead; reuse smem for the fp32 C buffer

    float* Cs = (float*)smbuf;           // [128][128]
    for (int j = 0; j < 8; j++)
        wmma::store_matrix_sync(Cs + (warp * 16) * 128 + j * 16, cfrag[j], 128,
                                wmma::mem_row_major);
    __syncthreads();

    // epilogue: thread t handles row t/2, 64 channels; pair-reduce projections
    int row = tid >> 1;
    int hh = tid & 1;
    int c0 = hh * 64;
    int grow = row0 + row;
    float p1 = 0.f, p2 = 0.f;
    __half2 hv[32];
    for (int j = 0; j < 32; j++) {
        float ox = Cs[row * 128 + c0 + 2 * j]     + bias[c0 + 2 * j];
        float oy = Cs[row * 128 + c0 + 2 * j + 1] + bias[c0 + 2 * j + 1];
        p1 += ox * aW[c0 + 2 * j]     + oy * aW[c0 + 2 * j + 1];
        p2 += ox * aW[D + c0 + 2 * j] + oy * aW[D + c0 + 2 * j + 1];
        hv[j] = __floats2half2_rn(ox, oy);
    }
    p1 += __shfl_xor_sync(0xffffffffu, p1, 1);
    p2 += __shfl_xor_sync(0xffffffffu, p2, 1);
    if (grow < n) {
        uint4* dst4 = (uint4*)(Z16 + (size_t)grow * D + c0);
        const uint4* src4 = (const uint4*)hv;
        for (int j = 0; j < 8; j++) dst4[j] = src4[j];
        if (hh == 0) { asrc[grow] = p1; adst[grow] = p2; }
    }
}

// ---------------- fused segment softmax + weighted gather ------------------
// One warp per dst node. Pass 1: online max+sum, caching the first 2 chunks'
// (e, src) in registers (covers deg<=64, i.e. ~all nodes at mean degree 32).
// Pass 2: 2 edges per step, 16 lanes x 16B LDG.128 per row; cached chunks
// skip the second asrc gather. outh != 0: write relu'd fp16 (next layer's
// GEMM input); else write fp32 to outf.
__global__ void aggregate_kernel(const __half* __restrict__ z16,
                                 const float* __restrict__ asrc,
                                 const float* __restrict__ adst,
                                 const int* __restrict__ off,
                                 const int* __restrict__ csr_src,
                                 const float* __restrict__ ab,
                                 float* __restrict__ outf,
                                 __half* __restrict__ outh, int n)
{
    int node = (blockIdx.x * blockDim.x + threadIdx.x) >> 5;
    int lane = threadIdx.x & 31;
    if (node >= n) return;
    int beg = off[node], end = off[node + 1];
    float advv = adst[node] + ab[0];

    // pass 1: online softmax statistics; cache chunks 0/1
    float ec0 = -1e30f, ec1 = -1e30f;
    int   sc0 = 0, sc1 = 0;
    float m = -1e30f, s = 0.f;
    {
        int ch = 0;
        for (int j0 = beg; j0 < end; j0 += 32) {
            int j = j0 + lane;
            float e = -1e30f;
            int sj = 0;
            if (j < end) {
                sj = csr_src[j];
                e = asrc[sj] + advv;
                e = (e > 0.f) ? e : 0.01f * e;
                if (e > m) { s = s * __expf(m - e) + 1.f; m = e; }
                else       { s += __expf(e - m); }
            }
            if (ch == 0) { ec0 = e; sc0 = sj; }
            else if (ch == 1) { ec1 = e; sc1 = sj; }
            ch++;
        }
    }
#pragma unroll
    for (int o = 16; o; o >>= 1) {
        float m2 = __shfl_xor_sync(0xffffffffu, m, o);
        float s2 = __shfl_xor_sync(0xffffffffu, s, o);
        float mn = fmaxf(m, m2);
        s = s * __expf(m - mn) + s2 * __expf(m2 - mn);
        m = mn;
    }
    float inv_s = (end > beg) ? 1.f / s : 0.f;

    // pass 2: weighted gather, 2 edges per step, 16B per lane
    float acc8[8] = {0.f, 0.f, 0.f, 0.f, 0.f, 0.f, 0.f, 0.f};
    int hf = lane >> 4;
    int chan = (lane & 15) * 8;
    {
        int ch = 0;
        for (int j0 = beg; j0 < end; j0 += 32) {
            int j = j0 + lane;
            float e;
            int sj;
            if (ch == 0) { e = ec0; sj = sc0; }
            else if (ch == 1) { e = ec1; sj = sc1; }
            else {
                e = -1e30f;
                sj = 0;
                if (j < end) {
                    sj = csr_src[j];
                    e = asrc[sj] + advv;
                    e = (e > 0.f) ? e : 0.01f * e;
                }
            }
            float alpha = (j < end) ? __expf(e - m) * inv_s : 0.f;
            int cnt = min(32, end - j0);
            int steps = (cnt + 1) >> 1;
#pragma unroll 4
            for (int t = 0; t < steps; t++) {
                float a  = __shfl_sync(0xffffffffu, alpha, 2 * t + hf);
                int   sn = __shfl_sync(0xffffffffu, sj,    2 * t + hf);
                uint4 raw = *(const uint4*)(z16 + (size_t)sn * D + chan);
                __half2 q0, q1, q2, q3;
                q0 = *reinterpret_cast<__half2*>(&raw.x);
                q1 = *reinterpret_cast<__half2*>(&raw.y);
                q2 = *reinterpret_cast<__half2*>(&raw.z);
                q3 = *reinterpret_cast<__half2*>(&raw.w);
                float2 f0 = __half22float2(q0);
                float2 f1 = __half22float2(q1);
                float2 f2 = __half22float2(q2);
                float2 f3 = __half22float2(q3);
                acc8[0] += a * f0.x;
                acc8[1] += a * f0.y;
                acc8[2] += a * f1.x;
                acc8[3] += a * f1.y;
                acc8[4] += a * f2.x;
                acc8[5] += a * f2.y;
                acc8[6] += a * f3.x;
                acc8[7] += a * f3.y;
            }
            ch++;
        }
    }
    // combine the two edge-halves
#pragma unroll
    for (int c = 0; c < 8; c++) {
        acc8[c] += __shfl_xor_sync(0xffffffffu, acc8[c], 16);
    }

    if (lane < 16) {
        if (outh != 0) {
            __half2 h0 = __floats2half2_rn(fmaxf(acc8[0], 0.f), fmaxf(acc8[1], 0.f));
            __half2 h1 = __floats2half2_rn(fmaxf(acc8[2], 0.f), fmaxf(acc8[3], 0.f));
            __half2 h2 = __floats2half2_rn(fmaxf(acc8[4], 0.f), fmaxf(acc8[5], 0.f));
            __half2 h3 = __floats2half2_rn(fmaxf(acc8[6], 0.f), fmaxf(acc8[7], 0.f));
            uint4 u;
            u.x = *reinterpret_cast<unsigned*>(&h0);
            u.y = *reinterpret_cast<unsigned*>(&h1);
            u.z = *reinterpret_cast<unsigned*>(&h2);
            u.w = *reinterpret_cast<unsigned*>(&h3);
            *(uint4*)(outh + (size_t)node * D + chan) = u;
        } else {
            *(float4*)(outf + (size_t)node * D + chan) =
                make_float4(acc8[0], acc8[1], acc8[2], acc8[3]);
            *(float4*)(outf + (size_t)node * D + chan + 4) =
                make_float4(acc8[4], acc8[5], acc8[6], acc8[7]);
        }
    }
}

// ---------------- launch ----------------------------------------------------
extern "C" void kernel_launch(void* const* d_in, const int* in_sizes, int n_in,
                              void* d_out, int out_size)
{
    const float* x   = (const float*)d_in[0];
    const int*   src = (const int*)d_in[1];
    const int*   dst = (const int*)d_in[2];
    // d_in[3] = t (unused)
    const float* W0  = (const float*)d_in[4];
    const float* b0  = (const float*)d_in[5];
    const float* aW0 = (const float*)d_in[6];
    const float* ab0 = (const float*)d_in[7];
    const float* W1  = (const float*)d_in[8];
    const float* b1  = (const float*)d_in[9];
    const float* aW1 = (const float*)d_in[10];
    const float* ab1 = (const float*)d_in[11];
    const float* W2  = (const float*)d_in[12];
    const float* b2  = (const float*)d_in[13];
    const float* aW2 = (const float*)d_in[14];
    const float* ab2 = (const float*)d_in[15];

    int n = in_sizes[0] / D;   // 50000
    int E = in_sizes[1];       // 1600000

    __half *x16, *z16, *w16;
    float *asrc, *adst;
    int *deg, *cur, *off, *csr;
    cudaGetSymbolAddress((void**)&x16,  g_x16);
    cudaGetSymbolAddress((void**)&z16,  g_z16);
    cudaGetSymbolAddress((void**)&w16,  g_w16);
    cudaGetSymbolAddress((void**)&asrc, g_asrc);
    cudaGetSymbolAddress((void**)&adst, g_adst);
    cudaGetSymbolAddress((void**)&deg,  g_deg);
    cudaGetSymbolAddress((void**)&cur,  g_cur);
    cudaGetSymbolAddress((void**)&off,  g_off);
    cudaGetSymbolAddress((void**)&csr,  g_csr_src);

    float* outf = (float*)d_out;

    // idempotent, host-side, not a stream op (safe under graph capture)
    cudaFuncSetAttribute(gemm_kernel, cudaFuncAttributeMaxDynamicSharedMemorySize,
                         GEMM_SMEM_BYTES);

    int tb = 256;
    // ---- CSR build ----
    zero_kernel<<<(n + tb - 1) / tb, tb>>>(deg, cur, n);
    hist_kernel<<<(E / 4 + tb - 1) / tb, tb>>>(dst, deg, E);
    scan_kernel<<<1, 1024>>>(deg, off, n);
    scatter_kernel<<<(E + tb - 1) / tb, tb>>>(src, dst, off, cur, csr, E);

    // ---- conversions: x and the three weight matrices to fp16 ----
    int n8x = n * D / 8;
    cvt_f2h_kernel<<<(n8x + tb - 1) / tb, tb>>>(x, x16, n8x);
    cvt_f2h_kernel<<<(2048 + tb - 1) / tb, tb>>>(W0, w16,             2048);
    cvt_f2h_kernel<<<(2048 + tb - 1) / tb, tb>>>(W1, w16 + D * D,     2048);
    cvt_f2h_kernel<<<(2048 + tb - 1) / tb, tb>>>(W2, w16 + 2 * D * D, 2048);

    int gemm_blocks = (n + 127) / 128;
    int warp_blocks = (n + 7) / 8;

    // ---- layer 0 (fp16 relu out -> x16) ----
    gemm_kernel<<<gemm_blocks, 256, GEMM_SMEM_BYTES>>>(x16, w16, b0, aW0, z16, asrc, adst, n);
    aggregate_kernel<<<warp_blocks, 256>>>(z16, asrc, adst, off, csr, ab0, 0, x16, n);
    // ---- layer 1 (fp16 relu out -> x16) ----
    gemm_kernel<<<gemm_blocks, 256, GEMM_SMEM_BYTES>>>(x16, w16 + D * D, b1, aW1, z16, asrc, adst, n);
    aggregate_kernel<<<warp_blocks, 256>>>(z16, asrc, adst, off, csr, ab1, 0, x16, n);
    // ---- layer 2 (fp32 out -> d_out) ----
    gemm_kernel<<<gemm_blocks, 256, GEMM_SMEM_BYTES>>>(x16, w16 + 2 * D * D, b2, aW2, z16, asrc, adst, n);
    aggregate_kernel<<<warp_blocks, 256>>>(z16, asrc, adst, off, csr, ab2, outf, 0, n);
}

// round 8
// speedup vs baseline: 1.4403x; 1.0629x over previous
#include <cuda_runtime.h>
#include <cuda_fp16.h>
#include <mma.h>

using namespace nvcuda;

// Problem constants (fixed by the dataset)
#define N_NODES 50000
#define N_EDGES 1600000
#define D 128

// ---------------- scratch (device globals; no allocation allowed) ----------
__device__ __align__(16) __half g_x16[N_NODES * D];  // fp16 GEMM input
__device__ __align__(16) __half g_z16[N_NODES * D];  // fp16 GEMM output / gather payload
__device__ __align__(16) __half g_w16[3 * D * D];    // fp16 weights
__device__ float g_asrc[N_NODES];
__device__ float g_adst[N_NODES];
__device__ int   g_deg[N_NODES];
__device__ int   g_cur[N_NODES];
__device__ int   g_off[N_NODES + 1];
__device__ int   g_csr_src[N_EDGES];

// ---------------- CSR build ------------------------------------------------
__global__ void zero_kernel(int* a, int* b, int n) {
    int i = blockIdx.x * blockDim.x + threadIdx.x;
    if (i < n) { a[i] = 0; b[i] = 0; }
}

__global__ void hist_kernel(const int* __restrict__ dst, int* __restrict__ deg, int E) {
    int i4 = (blockIdx.x * blockDim.x + threadIdx.x) * 4;
    if (i4 + 3 < E) {
        int4 v = *(const int4*)(dst + i4);
        atomicAdd(&deg[v.x], 1);
        atomicAdd(&deg[v.y], 1);
        atomicAdd(&deg[v.z], 1);
        atomicAdd(&deg[v.w], 1);
    } else {
        for (int i = i4; i < E; i++) atomicAdd(&deg[dst[i]], 1);
    }
}

// single-block exclusive scan: 1024 threads x 49 contiguous elems/thread
__global__ void scan_kernel(const int* __restrict__ deg, int* __restrict__ off, int n) {
    const int C = 49;  // 1024*49 = 50176 >= 50000
    __shared__ int wsum[32];
    int tid = threadIdx.x, lane = tid & 31, wid = tid >> 5;
    int base = tid * C;
    int s = 0;
    for (int u = 0; u < C; u++) {
        int i = base + u;
        if (i < n) s += deg[i];
    }
    int x = s;
#pragma unroll
    for (int o = 1; o < 32; o <<= 1) {
        int y = __shfl_up_sync(0xffffffffu, x, o);
        if (lane >= o) x += y;
    }
    if (lane == 31) wsum[wid] = x;
    __syncthreads();
    if (wid == 0) {
        int w = wsum[lane];
#pragma unroll
        for (int o = 1; o < 32; o <<= 1) {
            int y = __shfl_up_sync(0xffffffffu, w, o);
            if (lane >= o) w += y;
        }
        wsum[lane] = w;
    }
    __syncthreads();
    int run = x - s + (wid ? wsum[wid - 1] : 0);
    for (int u = 0; u < C; u++) {
        int i = base + u;
        if (i < n) { off[i] = run; run += deg[i]; }
    }
    if (tid == 1023) off[n] = run;
}

__global__ void scatter_kernel(const int* __restrict__ src, const int* __restrict__ dst,
                               const int* __restrict__ off, int* __restrict__ cur,
                               int* __restrict__ csr_src, int E) {
    int i = blockIdx.x * blockDim.x + threadIdx.x;
    if (i >= E) return;
    int d = dst[i];
    int p = off[d] + atomicAdd(&cur[d], 1);
    csr_src[p] = src[i];
}

// ---------------- fp32 -> fp16 conversions ----------------------------------
__global__ void cvt_x_kernel(const float* __restrict__ in, __half* __restrict__ out16,
                             int n8) {
    int i = blockIdx.x * blockDim.x + threadIdx.x;
    if (i >= n8) return;
    const float4* p = (const float4*)in + (size_t)i * 2;
    float4 a = p[0], b = p[1];
    __half2 h0 = __floats2half2_rn(a.x, a.y);
    __half2 h1 = __floats2half2_rn(a.z, a.w);
    __half2 h2 = __floats2half2_rn(b.x, b.y);
    __half2 h3 = __floats2half2_rn(b.z, b.w);
    uint4 u;
    u.x = *reinterpret_cast<unsigned*>(&h0);
    u.y = *reinterpret_cast<unsigned*>(&h1);
    u.z = *reinterpret_cast<unsigned*>(&h2);
    u.w = *reinterpret_cast<unsigned*>(&h3);
    *((uint4*)out16 + i) = u;
}

__global__ void cvt_w_kernel(const float* __restrict__ W0, const float* __restrict__ W1,
                             const float* __restrict__ W2, __half* __restrict__ w16) {
    int i = blockIdx.x * blockDim.x + threadIdx.x;  // 3 * 2048 vec8 chunks
    if (i >= 3 * 2048) return;
    int which = i >> 11, j = i & 2047;
    const float* W = (which == 0) ? W0 : ((which == 1) ? W1 : W2);
    const float4* p = (const float4*)W + (size_t)j * 2;
    float4 a = p[0], b = p[1];
    __half2 h0 = __floats2half2_rn(a.x, a.y);
    __half2 h1 = __floats2half2_rn(a.z, a.w);
    __half2 h2 = __floats2half2_rn(b.x, b.y);
    __half2 h3 = __floats2half2_rn(b.z, b.w);
    uint4 u;
    u.x = *reinterpret_cast<unsigned*>(&h0);
    u.y = *reinterpret_cast<unsigned*>(&h1);
    u.z = *reinterpret_cast<unsigned*>(&h2);
    u.w = *reinterpret_cast<unsigned*>(&h3);
    *((uint4*)(w16 + (size_t)which * D * D) + j) = u;
}

// ---------------- WMMA GEMM + fused attention projections -------------------
// Z16 = fp16(X16 @ W16^T + b); asrc/adst = Z @ aW halves from fp32 accums.
// Block: 128 rows, full N=128, full K=128 staged once. 8 warps, 16 rows each,
// 8 accumulator fragments per warp. Padded ld=136 halves for staging tiles.
// W is [n][k] row-major; as a col_major wmma matrix_b this gives
// B(k,n) = W[n][k] exactly.
#define LDP 136
#define GEMM_SMEM_BYTES (2 * 128 * LDP * 2)   // 69632; also covers 128*128*4 float C

__global__ __launch_bounds__(256) void gemm_kernel(
    const __half* __restrict__ X16, const __half* __restrict__ W16,
    const float* __restrict__ bias, const float* __restrict__ aW,
    __half* __restrict__ Z16, float* __restrict__ asrc, float* __restrict__ adst, int n)
{
    extern __shared__ __half smbuf[];
    __half* As = smbuf;                  // [128][LDP]
    __half* Ws = smbuf + 128 * LDP;      // [128][LDP]
    int tid = threadIdx.x;
    int row0 = blockIdx.x * 128;

    // stage X tile (zero-filled past n) and W, 8 x 16B chunks per thread each
    for (int i = 0; i < 8; i++) {
        int c = tid + i * 256;           // 0..2047
        int row = c >> 4;
        int k8 = c & 15;
        uint4 v = make_uint4(0u, 0u, 0u, 0u);
        int grow = row0 + row;
        if (grow < n) v = *(const uint4*)(X16 + (size_t)grow * D + k8 * 8);
        *(uint4*)(As + row * LDP + k8 * 8) = v;
        uint4 wv = *(const uint4*)(W16 + row * D + k8 * 8);
        *(uint4*)(Ws + row * LDP + k8 * 8) = wv;
    }
    __syncthreads();

    int warp = tid >> 5;
    wmma::fragment<wmma::accumulator, 16, 16, 16, float> cfrag[8];
    for (int j = 0; j < 8; j++) wmma::fill_fragment(cfrag[j], 0.0f);

    for (int k = 0; k < 8; k++) {
        wmma::fragment<wmma::matrix_a, 16, 16, 16, __half, wmma::row_major> afrag;
        wmma::load_matrix_sync(afrag, As + (warp * 16) * LDP + k * 16, LDP);
        for (int j = 0; j < 8; j++) {
            wmma::fragment<wmma::matrix_b, 16, 16, 16, __half, wmma::col_major> bfrag;
            wmma::load_matrix_sync(bfrag, Ws + (j * 16) * LDP + k * 16, LDP);
            wmma::mma_sync(cfrag[j], afrag, bfrag, cfrag[j]);
        }
    }
    __syncthreads();   // tiles dead; reuse smem for the fp32 C buffer

    float* Cs = (float*)smbuf;           // [128][128]
    for (int j = 0; j < 8; j++)
        wmma::store_matrix_sync(Cs + (warp * 16) * 128 + j * 16, cfrag[j], 128,
                                wmma::mem_row_major);
    __syncthreads();

    // epilogue: thread t handles row t/2, 64 channels; pair-reduce projections
    int row = tid >> 1;
    int hh = tid & 1;
    int c0 = hh * 64;
    int grow = row0 + row;
    float p1 = 0.f, p2 = 0.f;
    __half2 hv[32];
    for (int j = 0; j < 32; j++) {
        float ox = Cs[row * 128 + c0 + 2 * j]     + bias[c0 + 2 * j];
        float oy = Cs[row * 128 + c0 + 2 * j + 1] + bias[c0 + 2 * j + 1];
        p1 += ox * aW[c0 + 2 * j]     + oy * aW[c0 + 2 * j + 1];
        p2 += ox * aW[D + c0 + 2 * j] + oy * aW[D + c0 + 2 * j + 1];
        hv[j] = __floats2half2_rn(ox, oy);
    }
    p1 += __shfl_xor_sync(0xffffffffu, p1, 1);
    p2 += __shfl_xor_sync(0xffffffffu, p2, 1);
    if (grow < n) {
        uint4* dst4 = (uint4*)(Z16 + (size_t)grow * D + c0);
        const uint4* src4 = (const uint4*)hv;
        for (int j = 0; j < 8; j++) dst4[j] = src4[j];
        if (hh == 0) { asrc[grow] = p1; adst[grow] = p2; }
    }
}

// ---------------- fused segment softmax + weighted gather ------------------
// One warp per dst node. Fast path (deg <= 128, ~all nodes at mean deg 32):
// pass 1 stages (e, src) per edge into per-warp smem; pass 2a converts e ->
// alpha in place; pass 2b reads alpha/src from smem (no shfl chains, no
// second csr/asrc gather) and issues independent LDG.128 row loads, 2 edges
// per step, 16 lanes x 16B per row. Slow path recomputes (rare).
// outh != 0: write relu'd fp16; else fp32 to outf.
#define AGG_CAP 128

__global__ __launch_bounds__(256) void aggregate_kernel(
    const __half* __restrict__ z16,
    const float* __restrict__ asrc,
    const float* __restrict__ adst,
    const int* __restrict__ off,
    const int* __restrict__ csr_src,
    const float* __restrict__ ab,
    float* __restrict__ outf,
    __half* __restrict__ outh, int n)
{
    __shared__ float s_alpha[8][AGG_CAP + 2];
    __shared__ int   s_sj[8][AGG_CAP + 2];

    int node = (blockIdx.x * blockDim.x + threadIdx.x) >> 5;
    int lane = threadIdx.x & 31;
    int w = (threadIdx.x >> 5);
    if (node >= n) return;
    int beg = off[node], end = off[node + 1];
    int deg = end - beg;
    float advv = adst[node] + ab[0];

    int hf = lane >> 4;
    int chan = (lane & 15) * 8;
    float acc8[8] = {0.f, 0.f, 0.f, 0.f, 0.f, 0.f, 0.f, 0.f};
    float m = -1e30f, s = 0.f;

    if (deg <= AGG_CAP) {
        // ---- pass 1: gather e/src, stage to smem, online stats ----
        for (int idx = lane; idx < deg; idx += 32) {
            int sj = csr_src[beg + idx];
            float e = asrc[sj] + advv;
            e = (e > 0.f) ? e : 0.01f * e;
            s_alpha[w][idx] = e;
            s_sj[w][idx] = sj;
            if (e > m) { s = s * __expf(m - e) + 1.f; m = e; }
            else       { s += __expf(e - m); }
        }
#pragma unroll
        for (int o = 16; o; o >>= 1) {
            float m2 = __shfl_xor_sync(0xffffffffu, m, o);
            float s2 = __shfl_xor_sync(0xffffffffu, s, o);
            float mn = fmaxf(m, m2);
            s = s * __expf(m - mn) + s2 * __expf(m2 - mn);
            m = mn;
        }
        float inv_s = (deg > 0) ? 1.f / s : 0.f;
        // ---- pass 2a: e -> alpha in smem; pad one slot ----
        for (int idx = lane; idx < deg; idx += 32) {
            s_alpha[w][idx] = __expf(s_alpha[w][idx] - m) * inv_s;
        }
        if (lane == 0) { s_alpha[w][deg] = 0.f; s_sj[w][deg] = 0; }
        __syncwarp();
        // ---- pass 2b: weighted gather, 2 edges/step ----
        int steps = (deg + 1) >> 1;
#pragma unroll 4
        for (int t = 0; t < steps; t++) {
            int idx = 2 * t + hf;
            float a  = s_alpha[w][idx];
            int   sn = s_sj[w][idx];
            uint4 raw = *(const uint4*)(z16 + (size_t)sn * D + chan);
            __half2 q0 = *reinterpret_cast<__half2*>(&raw.x);
            __half2 q1 = *reinterpret_cast<__half2*>(&raw.y);
            __half2 q2 = *reinterpret_cast<__half2*>(&raw.z);
            __half2 q3 = *reinterpret_cast<__half2*>(&raw.w);
            float2 f0 = __half22float2(q0);
            float2 f1 = __half22float2(q1);
            float2 f2 = __half22float2(q2);
            float2 f3 = __half22float2(q3);
            acc8[0] += a * f0.x;
            acc8[1] += a * f0.y;
            acc8[2] += a * f1.x;
            acc8[3] += a * f1.y;
            acc8[4] += a * f2.x;
            acc8[5] += a * f2.y;
            acc8[6] += a * f3.x;
            acc8[7] += a * f3.y;
        }
    } else {
        // ---- slow path (deg > 128): recompute, as in R7 ----
        for (int j = beg + lane; j < end; j += 32) {
            float e = asrc[csr_src[j]] + advv;
            e = (e > 0.f) ? e : 0.01f * e;
            if (e > m) { s = s * __expf(m - e) + 1.f; m = e; }
            else       { s += __expf(e - m); }
        }
#pragma unroll
        for (int o = 16; o; o >>= 1) {
            float m2 = __shfl_xor_sync(0xffffffffu, m, o);
            float s2 = __shfl_xor_sync(0xffffffffu, s, o);
            float mn = fmaxf(m, m2);
            s = s * __expf(m - mn) + s2 * __expf(m2 - mn);
            m = mn;
        }
        float inv_s = 1.f / s;
        for (int j0 = beg; j0 < end; j0 += 32) {
            int j = j0 + lane;
            float alpha = 0.f;
            int sj = 0;
            if (j < end) {
                sj = csr_src[j];
                float e = asrc[sj] + advv;
                e = (e > 0.f) ? e : 0.01f * e;
                alpha = __expf(e - m) * inv_s;
            }
            int cnt = min(32, end - j0);
            int steps = (cnt + 1) >> 1;
            for (int t = 0; t < steps; t++) {
                float a  = __shfl_sync(0xffffffffu, alpha, 2 * t + hf);
                int   sn = __shfl_sync(0xffffffffu, sj,    2 * t + hf);
                uint4 raw = *(const uint4*)(z16 + (size_t)sn * D + chan);
                __half2 q0 = *reinterpret_cast<__half2*>(&raw.x);
                __half2 q1 = *reinterpret_cast<__half2*>(&raw.y);
                __half2 q2 = *reinterpret_cast<__half2*>(&raw.z);
                __half2 q3 = *reinterpret_cast<__half2*>(&raw.w);
                float2 f0 = __half22float2(q0);
                float2 f1 = __half22float2(q1);
                float2 f2 = __half22float2(q2);
                float2 f3 = __half22float2(q3);
                acc8[0] += a * f0.x;
                acc8[1] += a * f0.y;
                acc8[2] += a * f1.x;
                acc8[3] += a * f1.y;
                acc8[4] += a * f2.x;
                acc8[5] += a * f2.y;
                acc8[6] += a * f3.x;
                acc8[7] += a * f3.y;
            }
        }
    }

    // combine the two edge-halves
#pragma unroll
    for (int c = 0; c < 8; c++) {
        acc8[c] += __shfl_xor_sync(0xffffffffu, acc8[c], 16);
    }

    if (lane < 16) {
        if (outh != 0) {
            __half2 h0 = __floats2half2_rn(fmaxf(acc8[0], 0.f), fmaxf(acc8[1], 0.f));
            __half2 h1 = __floats2half2_rn(fmaxf(acc8[2], 0.f), fmaxf(acc8[3], 0.f));
            __half2 h2 = __floats2half2_rn(fmaxf(acc8[4], 0.f), fmaxf(acc8[5], 0.f));
            __half2 h3 = __floats2half2_rn(fmaxf(acc8[6], 0.f), fmaxf(acc8[7], 0.f));
            uint4 u;
            u.x = *reinterpret_cast<unsigned*>(&h0);
            u.y = *reinterpret_cast<unsigned*>(&h1);
            u.z = *reinterpret_cast<unsigned*>(&h2);
            u.w = *reinterpret_cast<unsigned*>(&h3);
            *(uint4*)(outh + (size_t)node * D + chan) = u;
        } else {
            *(float4*)(outf + (size_t)node * D + chan) =
                make_float4(acc8[0], acc8[1], acc8[2], acc8[3]);
            *(float4*)(outf + (size_t)node * D + chan + 4) =
                make_float4(acc8[4], acc8[5], acc8[6], acc8[7]);
        }
    }
}

// ---------------- launch ----------------------------------------------------
extern "C" void kernel_launch(void* const* d_in, const int* in_sizes, int n_in,
                              void* d_out, int out_size)
{
    const float* x   = (const float*)d_in[0];
    const int*   src = (const int*)d_in[1];
    const int*   dst = (const int*)d_in[2];
    // d_in[3] = t (unused)
    const float* W0  = (const float*)d_in[4];
    const float* b0  = (const float*)d_in[5];
    const float* aW0 = (const float*)d_in[6];
    const float* ab0 = (const float*)d_in[7];
    const float* W1  = (const float*)d_in[8];
    const float* b1  = (const float*)d_in[9];
    const float* aW1 = (const float*)d_in[10];
    const float* ab1 = (const float*)d_in[11];
    const float* W2  = (const float*)d_in[12];
    const float* b2  = (const float*)d_in[13];
    const float* aW2 = (const float*)d_in[14];
    const float* ab2 = (const float*)d_in[15];

    int n = in_sizes[0] / D;   // 50000
    int E = in_sizes[1];       // 1600000

    __half *x16, *z16, *w16;
    float *asrc, *adst;
    int *deg, *cur, *off, *csr;
    cudaGetSymbolAddress((void**)&x16,  g_x16);
    cudaGetSymbolAddress((void**)&z16,  g_z16);
    cudaGetSymbolAddress((void**)&w16,  g_w16);
    cudaGetSymbolAddress((void**)&asrc, g_asrc);
    cudaGetSymbolAddress((void**)&adst, g_adst);
    cudaGetSymbolAddress((void**)&deg,  g_deg);
    cudaGetSymbolAddress((void**)&cur,  g_cur);
    cudaGetSymbolAddress((void**)&off,  g_off);
    cudaGetSymbolAddress((void**)&csr,  g_csr_src);

    float* outf = (float*)d_out;

    // idempotent, host-side, not a stream op (safe under graph capture)
    cudaFuncSetAttribute(gemm_kernel, cudaFuncAttributeMaxDynamicSharedMemorySize,
                         GEMM_SMEM_BYTES);

    int tb = 256;
    // ---- CSR build ----
    zero_kernel<<<(n + tb - 1) / tb, tb>>>(deg, cur, n);
    hist_kernel<<<(E / 4 + tb - 1) / tb, tb>>>(dst, deg, E);
    scan_kernel<<<1, 1024>>>(deg, off, n);
    scatter_kernel<<<(E + tb - 1) / tb, tb>>>(src, dst, off, cur, csr, E);

    // ---- conversions: x and the three weight matrices to fp16 ----
    int n8x = n * D / 8;
    cvt_x_kernel<<<(n8x + tb - 1) / tb, tb>>>(x, x16, n8x);
    cvt_w_kernel<<<(3 * 2048 + tb - 1) / tb, tb>>>(W0, W1, W2, w16);

    int gemm_blocks = (n + 127) / 128;
    int warp_blocks = (n + 7) / 8;

    // ---- layer 0 (fp16 relu out -> x16) ----
    gemm_kernel<<<gemm_blocks, 256, GEMM_SMEM_BYTES>>>(x16, w16, b0, aW0, z16, asrc, adst, n);
    aggregate_kernel<<<warp_blocks, 256>>>(z16, asrc, adst, off, csr, ab0, 0, x16, n);
    // ---- layer 1 (fp16 relu out -> x16) ----
    gemm_kernel<<<gemm_blocks, 256, GEMM_SMEM_BYTES>>>(x16, w16 + D * D, b1, aW1, z16, asrc, adst, n);
    aggregate_kernel<<<warp_blocks, 256>>>(z16, asrc, adst, off, csr, ab1, 0, x16, n);
    // ---- layer 2 (fp32 out -> d_out) ----
    gemm_kernel<<<gemm_blocks, 256, GEMM_SMEM_BYTES>>>(x16, w16 + 2 * D * D, b2, aW2, z16, asrc, adst, n);
    aggregate_kernel<<<warp_blocks, 256>>>(z16, asrc, adst, off, csr, ab2, outf, 0, n);
}